// round 11
// baseline (speedup 1.0000x reference)
#include <cuda_runtime.h>
#include <cstdint>

#define NN 100000
#define NE 1600000
#define D 128
#define EDIM 16
#define SCAN_BLK 1024
#define NSCAN ((NN + SCAN_BLK - 1) / SCAN_BLK)   // 98
#define GS 132                                    // smem row stride (floats)

// ---------------------------------------------------------------------------
// Scratch inside d_out's eh region (E = out + NN*D, 25.6M floats = 102MB).
// eh copy runs LAST and overwrites it.
// ---------------------------------------------------------------------------
#define AGG_OFF   0
#define ESRC_OFF  ((size_t)NN * D)
#define CNT_OFF   (ESRC_OFF + NE)
#define OFF_OFF   (CNT_OFF + NN)
#define CUR_OFF   (OFF_OFF + NN)
#define BSUM_OFF  (CUR_OFF + NN)
#define DIS_OFF   (BSUM_OFF + 128)

// ---------------------------------------------------------------------------
// tf32 helpers: split f32 into hi/lo tf32 pair (3xTF32 scheme)
// ---------------------------------------------------------------------------
__device__ __forceinline__ void split_tf32(float x, uint32_t& h, uint32_t& l) {
    asm("cvt.rna.tf32.f32 %0, %1;" : "=r"(h) : "f"(x));
    float r = x - __uint_as_float(h);
    asm("cvt.rna.tf32.f32 %0, %1;" : "=r"(l) : "f"(r));
}
__device__ __forceinline__ void mma_tf32(float* c, const uint32_t* a,
                                         const uint32_t* b) {
    asm volatile(
        "mma.sync.aligned.m16n8k8.row.col.f32.tf32.tf32.f32 "
        "{%0,%1,%2,%3}, {%4,%5,%6,%7}, {%8,%9}, {%0,%1,%2,%3};"
        : "+f"(c[0]), "+f"(c[1]), "+f"(c[2]), "+f"(c[3])
        : "r"(a[0]), "r"(a[1]), "r"(a[2]), "r"(a[3]), "r"(b[0]), "r"(b[1]));
}

// ---------------------------------------------------------------------------
// Graph prep kernels (from the passing R7 pipeline)
// ---------------------------------------------------------------------------
__global__ void zero_cnt_kernel(int* __restrict__ cnt) {
    int i = blockIdx.x * blockDim.x + threadIdx.x;
    if (i < NN) cnt[i] = 0;
}

__global__ void count_kernel(const int* __restrict__ dst, int* __restrict__ cnt) {
    int e = blockIdx.x * blockDim.x + threadIdx.x;
    if (e < NE) atomicAdd(&cnt[dst[e]], 1);
}

__global__ __launch_bounds__(SCAN_BLK) void scan1_kernel(
    const int* __restrict__ cnt, int* __restrict__ off, int* __restrict__ bsum)
{
    __shared__ int s[SCAN_BLK];
    int gid = blockIdx.x * SCAN_BLK + threadIdx.x;
    int v = (gid < NN) ? cnt[gid] : 0;
    s[threadIdx.x] = v;
    __syncthreads();
    #pragma unroll
    for (int o = 1; o < SCAN_BLK; o <<= 1) {
        int t = (threadIdx.x >= o) ? s[threadIdx.x - o] : 0;
        __syncthreads();
        s[threadIdx.x] += t;
        __syncthreads();
    }
    if (gid < NN) off[gid] = s[threadIdx.x] - v;
    if (threadIdx.x == SCAN_BLK - 1) bsum[blockIdx.x] = s[SCAN_BLK - 1];
}

__global__ void scan2_kernel(int* __restrict__ bsum) {
    __shared__ int s[128];
    int tid = threadIdx.x;
    int v = (tid < NSCAN) ? bsum[tid] : 0;
    s[tid] = v;
    __syncthreads();
    #pragma unroll
    for (int o = 1; o < 128; o <<= 1) {
        int t = (tid >= o) ? s[tid - o] : 0;
        __syncthreads();
        s[tid] += t;
        __syncthreads();
    }
    if (tid < NSCAN) bsum[tid] = s[tid] - v;
}

__global__ void finalize_kernel(const int* __restrict__ cnt,
                                const int* __restrict__ bsum,
                                int* __restrict__ off, int* __restrict__ cur,
                                float* __restrict__ dis)
{
    int i = blockIdx.x * blockDim.x + threadIdx.x;
    if (i < NN) {
        int o = off[i] + bsum[i >> 10];
        off[i] = o;
        cur[i] = o;
        int c = cnt[i];
        dis[i] = (c > 0) ? rsqrtf((float)c) : 0.f;
    }
}

__global__ void bucket_kernel(const int* __restrict__ src,
                              const int* __restrict__ dst,
                              int* __restrict__ cur, int* __restrict__ esrc)
{
    int e = blockIdx.x * blockDim.x + threadIdx.x;
    if (e < NE) {
        int d = dst[e];
        int pos = atomicAdd(&cur[d], 1);
        esrc[pos] = src[e];
    }
}

__global__ __launch_bounds__(256) void aggregate_kernel(
    const float* __restrict__ nh, const int* __restrict__ esrc,
    const int* __restrict__ off, const int* __restrict__ cnt,
    const float* __restrict__ dis, float* __restrict__ agg)
{
    int n = (blockIdx.x * blockDim.x + threadIdx.x) >> 5;
    int lane = threadIdx.x & 31;
    if (n >= NN) return;
    int beg = off[n];
    int c = cnt[n];
    const float4* nh4 = (const float4*)nh;
    float4 acc = make_float4(0.f, 0.f, 0.f, 0.f);
    #pragma unroll 4
    for (int i = 0; i < c; i++) {
        int s = esrc[beg + i];
        float sc = dis[s];
        float4 v = nh4[(size_t)s * (D / 4) + lane];
        acc.x += sc * v.x; acc.y += sc * v.y;
        acc.z += sc * v.z; acc.w += sc * v.w;
    }
    float dn = dis[n];
    acc.x *= dn; acc.y *= dn; acc.z *= dn; acc.w *= dn;
    ((float4*)agg)[(size_t)n * (D / 4) + lane] = acc;
}

// ---------------------------------------------------------------------------
// tf32 tensor-core GEMM layer: C = act(A @ W + b), M-tile = 128, N = K = 128.
// 3xTF32: D = Ah*Bh + Ah*Bl + Al*Bh with f32 accumulation (~2^-22 error).
// 256 threads / 8 warps; warp w owns rows 16w..16w+15, all 128 columns.
// Smem: A tile f32 (split on the fly), W pre-split hi/lo (transposed to
// [n][k], conflict-free stride 132). In-place (C == A) is safe: each CTA
// reads only its own rows into smem before writing them.
// ---------------------------------------------------------------------------
__global__ __launch_bounds__(256) void gemm_tf32_kernel(
    const float* __restrict__ A, const float* __restrict__ W,
    const float* __restrict__ bias, float* __restrict__ C, int relu)
{
    extern __shared__ float sh[];
    float* As = sh;                 // 128 x GS  (f32)
    float* Wh = sh + 128 * GS;      // 128 x GS  (tf32-hi bits as f32 slots)
    float* Wl = sh + 2 * 128 * GS;  // 128 x GS  (tf32-lo)

    int tid = threadIdx.x;
    int m0 = blockIdx.x * 128;

    // Load A tile (coalesced float4), clamp overflow rows (last CTA only)
    for (int idx = tid; idx < 128 * 32; idx += 256) {
        int r = idx >> 5, q = idx & 31;
        int row = m0 + r;
        if (row >= NN) row = NN - 1;
        float4 v = ((const float4*)(A + (size_t)row * D))[q];
        float* p = As + r * GS + q * 4;
        p[0] = v.x; p[1] = v.y; p[2] = v.z; p[3] = v.w;
    }
    // Load W transposed + pre-split: Wh/Wl[n*GS + k] = split(W[k*128 + n])
    for (int idx = tid; idx < 128 * 32; idx += 256) {
        int k = idx >> 5, q = idx & 31;
        float4 v = ((const float4*)(W + (size_t)k * D))[q];
        int n = q * 4;
        uint32_t h, l;
        split_tf32(v.x, h, l);
        Wh[(n + 0) * GS + k] = __uint_as_float(h); Wl[(n + 0) * GS + k] = __uint_as_float(l);
        split_tf32(v.y, h, l);
        Wh[(n + 1) * GS + k] = __uint_as_float(h); Wl[(n + 1) * GS + k] = __uint_as_float(l);
        split_tf32(v.z, h, l);
        Wh[(n + 2) * GS + k] = __uint_as_float(h); Wl[(n + 2) * GS + k] = __uint_as_float(l);
        split_tf32(v.w, h, l);
        Wh[(n + 3) * GS + k] = __uint_as_float(h); Wl[(n + 3) * GS + k] = __uint_as_float(l);
    }
    __syncthreads();

    int w = tid >> 5, lane = tid & 31;
    int gid = lane >> 2, tig = lane & 3;
    int r0 = w * 16 + gid;          // fragment row (a0/a2); a1/a3 use r0+8

    float acc[64];
    #pragma unroll
    for (int i = 0; i < 64; i++) acc[i] = 0.f;

    #pragma unroll 1
    for (int kc = 0; kc < 16; kc++) {
        int k0 = kc * 8 + tig;
        uint32_t ah[4], al[4];
        split_tf32(As[r0 * GS + k0],           ah[0], al[0]);
        split_tf32(As[(r0 + 8) * GS + k0],     ah[1], al[1]);
        split_tf32(As[r0 * GS + k0 + 4],       ah[2], al[2]);
        split_tf32(As[(r0 + 8) * GS + k0 + 4], ah[3], al[3]);
        #pragma unroll
        for (int nc = 0; nc < 16; nc++) {
            int n = nc * 8 + gid;
            uint32_t bh[2], bl[2];
            bh[0] = __float_as_uint(Wh[n * GS + k0]);
            bh[1] = __float_as_uint(Wh[n * GS + k0 + 4]);
            bl[0] = __float_as_uint(Wl[n * GS + k0]);
            bl[1] = __float_as_uint(Wl[n * GS + k0 + 4]);
            mma_tf32(acc + nc * 4, ah, bh);
            mma_tf32(acc + nc * 4, ah, bl);
            mma_tf32(acc + nc * 4, al, bh);
        }
    }

    // Epilogue: bias + optional relu, float2 stores (c-frag layout)
    int row_a = m0 + w * 16 + gid;
    int row_b = row_a + 8;
    #pragma unroll
    for (int nc = 0; nc < 16; nc++) {
        int col = nc * 8 + tig * 2;
        float2 bs = *(const float2*)(bias + col);
        float2 v0 = make_float2(acc[nc * 4 + 0] + bs.x, acc[nc * 4 + 1] + bs.y);
        float2 v1 = make_float2(acc[nc * 4 + 2] + bs.x, acc[nc * 4 + 3] + bs.y);
        if (relu) {
            v0.x = fmaxf(v0.x, 0.f); v0.y = fmaxf(v0.y, 0.f);
            v1.x = fmaxf(v1.x, 0.f); v1.y = fmaxf(v1.y, 0.f);
        }
        if (row_a < NN) *(float2*)(C + (size_t)row_a * D + col) = v0;
        if (row_b < NN) *(float2*)(C + (size_t)row_b * D + col) = v1;
    }
}

// ---------------------------------------------------------------------------
__global__ void copy_eh_kernel(const float4* __restrict__ src,
                               float4* __restrict__ dst, int n4) {
    int i = blockIdx.x * blockDim.x + threadIdx.x;
    int stride = gridDim.x * blockDim.x;
    for (; i < n4; i += stride) dst[i] = src[i];
}

// ---------------------------------------------------------------------------
extern "C" void kernel_launch(void* const* d_in, const int* in_sizes, int n_in,
                              void* d_out, int out_size) {
    const float* nh = (const float*)d_in[0];
    const float* eh = (const float*)d_in[1];
    const int*   ei = (const int*)d_in[2];   // INT32 (JAX x64-disabled)
    const float* W1 = (const float*)d_in[3];
    const float* b1 = (const float*)d_in[4];
    const float* W2 = (const float*)d_in[5];
    const float* b2 = (const float*)d_in[6];
    float* out = (float*)d_out;

    const int* src = ei;
    const int* dst = ei + NE;

    float* E    = out + (size_t)NN * D;
    float* agg  = E + AGG_OFF;
    int*   esrc = (int*)(E + ESRC_OFF);
    int*   cnt  = (int*)(E + CNT_OFF);
    int*   off  = (int*)(E + OFF_OFF);
    int*   cur  = (int*)(E + CUR_OFF);
    int*   bsum = (int*)(E + BSUM_OFF);
    float* dis  = E + DIS_OFF;

    const int gemm_smem = 3 * 128 * GS * 4;   // 198KB dynamic
    cudaFuncSetAttribute(gemm_tf32_kernel,
                         cudaFuncAttributeMaxDynamicSharedMemorySize, gemm_smem);

    zero_cnt_kernel<<<(NN + 255) / 256, 256>>>(cnt);
    count_kernel<<<(NE + 255) / 256, 256>>>(dst, cnt);
    scan1_kernel<<<NSCAN, SCAN_BLK>>>(cnt, off, bsum);
    scan2_kernel<<<1, 128>>>(bsum);
    finalize_kernel<<<(NN + 255) / 256, 256>>>(cnt, bsum, off, cur, dis);
    bucket_kernel<<<(NE + 255) / 256, 256>>>(src, dst, cur, esrc);
    aggregate_kernel<<<(NN * 32 + 255) / 256, 256>>>(nh, esrc, off, cnt, dis, agg);

    const int gtiles = (NN + 127) / 128;      // 782
    gemm_tf32_kernel<<<gtiles, 256, gemm_smem>>>(agg, W1, b1, agg, 1);
    gemm_tf32_kernel<<<gtiles, 256, gemm_smem>>>(agg, W2, b2, out, 0);

    copy_eh_kernel<<<2048, 256>>>((const float4*)eh, (float4*)E, NE * EDIM / 4);
}

// round 14
// speedup vs baseline: 1.4592x; 1.4592x over previous
#include <cuda_runtime.h>
#include <cstdint>

#define NN 100000
#define NE 1600000
#define D 128
#define EDIM 16
#define TILE_M 32
#define SCAN_BLK 1024
#define NSCAN ((NN + SCAN_BLK - 1) / SCAN_BLK)   // 98

// Node chunking for pipeline overlap (multiples of TILE_M)
#define CHA 49984            // chunk A rows (1562 tiles)
#define CHB (NN - CHA)       // chunk B rows (1563 tiles)

// ---------------------------------------------------------------------------
// Scratch: ONLY the CSR arrays live in d_out's eh region (E = out+NN*D).
//   esrc : E[0 .. 1,600,000)        ints
//   cnt  : E[1,600,000 .. 1,700,000)
//   off  : E[1,700,000 .. 1,800,000)
//   cur  : E[1,800,000 .. 1,900,000)
//   bsum : E[1,900,000 .. 1,900,128)
//   dis  : E[1,900,128 .. 2,000,128)   <- ends BELOW CUT (R13 bug: it didn't)
// CUT = 2,000,256: eh[CUT..] copied early on s2 (disjoint from ALL scratch),
// eh[0..CUT) copied on the main stream after the last CSR reader.
// ---------------------------------------------------------------------------
#define ESRC_OFF  0
#define CNT_OFF   1600000
#define OFF_OFF   1700000
#define CUR_OFF   1800000
#define BSUM_OFF  1900000
#define DIS_OFF   1900128
#define CUT       2000256

// ---------------------------------------------------------------------------
__global__ void zero_cnt_kernel(int* __restrict__ cnt) {
    int i = blockIdx.x * blockDim.x + threadIdx.x;
    if (i < NN) cnt[i] = 0;
}

__global__ void count_kernel(const int* __restrict__ dst, int* __restrict__ cnt) {
    int e = blockIdx.x * blockDim.x + threadIdx.x;
    if (e < NE) atomicAdd(&cnt[dst[e]], 1);
}

__global__ __launch_bounds__(SCAN_BLK) void scan1_kernel(
    const int* __restrict__ cnt, int* __restrict__ off, int* __restrict__ bsum)
{
    __shared__ int s[SCAN_BLK];
    int gid = blockIdx.x * SCAN_BLK + threadIdx.x;
    int v = (gid < NN) ? cnt[gid] : 0;
    s[threadIdx.x] = v;
    __syncthreads();
    #pragma unroll
    for (int o = 1; o < SCAN_BLK; o <<= 1) {
        int t = (threadIdx.x >= o) ? s[threadIdx.x - o] : 0;
        __syncthreads();
        s[threadIdx.x] += t;
        __syncthreads();
    }
    if (gid < NN) off[gid] = s[threadIdx.x] - v;
    if (threadIdx.x == SCAN_BLK - 1) bsum[blockIdx.x] = s[SCAN_BLK - 1];
}

__global__ void scan2_kernel(int* __restrict__ bsum) {
    __shared__ int s[128];
    int tid = threadIdx.x;
    int v = (tid < NSCAN) ? bsum[tid] : 0;
    s[tid] = v;
    __syncthreads();
    #pragma unroll
    for (int o = 1; o < 128; o <<= 1) {
        int t = (tid >= o) ? s[tid - o] : 0;
        __syncthreads();
        s[tid] += t;
        __syncthreads();
    }
    if (tid < NSCAN) bsum[tid] = s[tid] - v;
}

__global__ void finalize_kernel(const int* __restrict__ cnt,
                                const int* __restrict__ bsum,
                                int* __restrict__ off, int* __restrict__ cur,
                                float* __restrict__ dis)
{
    int i = blockIdx.x * blockDim.x + threadIdx.x;
    if (i < NN) {
        int o = off[i] + bsum[i >> 10];
        off[i] = o;
        cur[i] = o;
        int c = cnt[i];
        dis[i] = (c > 0) ? rsqrtf((float)c) : 0.f;
    }
}

__global__ void bucket_kernel(const int* __restrict__ src,
                              const int* __restrict__ dst,
                              int* __restrict__ cur, int* __restrict__ esrc)
{
    int e = blockIdx.x * blockDim.x + threadIdx.x;
    if (e < NE) {
        int d = dst[e];
        int pos = atomicAdd(&cur[d], 1);
        esrc[pos] = src[e];
    }
}

// ---------------------------------------------------------------------------
// Aggregate nodes [base, base+nnode): one warp per node, lane = one float4.
// agg[n] = dis[n] * sum_{e in CSR[n]} dis[src_e] * nh[src_e] -> written to out
// ---------------------------------------------------------------------------
__global__ __launch_bounds__(256) void aggregate_kernel(
    const float* __restrict__ nh, const int* __restrict__ esrc,
    const int* __restrict__ off, const int* __restrict__ cnt,
    const float* __restrict__ dis, float* __restrict__ agg,
    int base, int nnode)
{
    int n = ((blockIdx.x * blockDim.x + threadIdx.x) >> 5);
    int lane = threadIdx.x & 31;
    if (n >= nnode) return;
    n += base;
    int beg = off[n];
    int c = cnt[n];
    const float4* nh4 = (const float4*)nh;
    float4 acc = make_float4(0.f, 0.f, 0.f, 0.f);
    #pragma unroll 4
    for (int i = 0; i < c; i++) {
        int s = esrc[beg + i];
        float sc = dis[s];
        float4 v = nh4[(size_t)s * (D / 4) + lane];
        acc.x += sc * v.x; acc.y += sc * v.y;
        acc.z += sc * v.z; acc.w += sc * v.w;
    }
    float dn = dis[n];
    acc.x *= dn; acc.y *= dn; acc.z *= dn; acc.w *= dn;
    ((float4*)agg)[(size_t)n * (D / 4) + lane] = acc;
}

// ---------------------------------------------------------------------------
// Fused in-place 2-layer MLP (plain FFMA — proven R7 config).
// Rows [base + 32*blk, +32): read tile -> layer1 (h in smem) -> layer2 ->
// overwrite same rows. In-place safe (CTA-private rows).
// ---------------------------------------------------------------------------
__global__ __launch_bounds__(128) void mlp_fused_kernel(
    float* __restrict__ io,
    const float* __restrict__ W1, const float* __restrict__ b1,
    const float* __restrict__ W2, const float* __restrict__ b2,
    int base)
{
    __shared__ float As[TILE_M * 129];
    __shared__ float Hs[TILE_M * 129];

    int tid = threadIdx.x;
    int m0 = base + blockIdx.x * TILE_M;
    int cg = tid & 31;
    int rg = tid >> 5;

    for (int idx = tid; idx < TILE_M * D; idx += 128) {
        int r = idx >> 7, c = idx & 127;
        As[r * 129 + c] = io[(size_t)(m0 + r) * D + c];
    }
    __syncthreads();

    float acc[8][4];

    // Layer 1: h = relu(A @ W1 + b1) -> Hs (scalar stores)
    {
        float4 bias = ((const float4*)b1)[cg];
        #pragma unroll
        for (int m = 0; m < 8; m++) {
            acc[m][0] = bias.x; acc[m][1] = bias.y;
            acc[m][2] = bias.z; acc[m][3] = bias.w;
        }
        const float* Arow = As + rg * 8 * 129;
        const float4* Wv = (const float4*)W1;
        #pragma unroll 4
        for (int i = 0; i < D; i++) {
            float4 w = Wv[i * 32 + cg];
            #pragma unroll
            for (int m = 0; m < 8; m++) {
                float a = Arow[m * 129 + i];
                acc[m][0] += a * w.x; acc[m][1] += a * w.y;
                acc[m][2] += a * w.z; acc[m][3] += a * w.w;
            }
        }
        float* Hrow = Hs + rg * 8 * 129 + 4 * cg;
        #pragma unroll
        for (int m = 0; m < 8; m++) {
            Hrow[m * 129 + 0] = fmaxf(acc[m][0], 0.f);
            Hrow[m * 129 + 1] = fmaxf(acc[m][1], 0.f);
            Hrow[m * 129 + 2] = fmaxf(acc[m][2], 0.f);
            Hrow[m * 129 + 3] = fmaxf(acc[m][3], 0.f);
        }
    }
    __syncthreads();

    // Layer 2: out = h @ W2 + b2 -> overwrite io rows
    {
        float4 bias = ((const float4*)b2)[cg];
        #pragma unroll
        for (int m = 0; m < 8; m++) {
            acc[m][0] = bias.x; acc[m][1] = bias.y;
            acc[m][2] = bias.z; acc[m][3] = bias.w;
        }
        const float* Hrow = Hs + rg * 8 * 129;
        const float4* Wv = (const float4*)W2;
        #pragma unroll 4
        for (int i = 0; i < D; i++) {
            float4 w = Wv[i * 32 + cg];
            #pragma unroll
            for (int m = 0; m < 8; m++) {
                float a = Hrow[m * 129 + i];
                acc[m][0] += a * w.x; acc[m][1] += a * w.y;
                acc[m][2] += a * w.z; acc[m][3] += a * w.w;
            }
        }
        #pragma unroll
        for (int m = 0; m < 8; m++) {
            float4 r = make_float4(acc[m][0], acc[m][1], acc[m][2], acc[m][3]);
            ((float4*)(io + (size_t)(m0 + rg * 8 + m) * D))[cg] = r;
        }
    }
}

// ---------------------------------------------------------------------------
__global__ void copy_eh_kernel(const float4* __restrict__ src,
                               float4* __restrict__ dst, int n4) {
    int i = blockIdx.x * blockDim.x + threadIdx.x;
    int stride = gridDim.x * blockDim.x;
    for (; i < n4; i += stride) dst[i] = src[i];
}

// ---------------------------------------------------------------------------
extern "C" void kernel_launch(void* const* d_in, const int* in_sizes, int n_in,
                              void* d_out, int out_size) {
    const float* nh = (const float*)d_in[0];
    const float* eh = (const float*)d_in[1];
    const int*   ei = (const int*)d_in[2];   // INT32 (JAX x64-disabled)
    const float* W1 = (const float*)d_in[3];
    const float* b1 = (const float*)d_in[4];
    const float* W2 = (const float*)d_in[5];
    const float* b2 = (const float*)d_in[6];
    float* out = (float*)d_out;

    const int* src = ei;
    const int* dst = ei + NE;

    float* E    = out + (size_t)NN * D;
    int*   esrc = (int*)(E + ESRC_OFF);
    int*   cnt  = (int*)(E + CNT_OFF);
    int*   off  = (int*)(E + OFF_OFF);
    int*   cur  = (int*)(E + CUR_OFF);
    int*   bsum = (int*)(E + BSUM_OFF);
    float* dis  = E + DIS_OFF;

    // Side stream + events (host-side objects only; graph-capture legal)
    cudaStream_t s2;
    cudaStreamCreateWithFlags(&s2, cudaStreamNonBlocking);
    cudaEvent_t evRoot, evAggA, evS2;
    cudaEventCreateWithFlags(&evRoot, cudaEventDisableTiming);
    cudaEventCreateWithFlags(&evAggA, cudaEventDisableTiming);
    cudaEventCreateWithFlags(&evS2,   cudaEventDisableTiming);

    // Fork: eh tail copy (disjoint from all scratch now) runs on s2
    cudaEventRecord(evRoot, 0);
    cudaStreamWaitEvent(s2, evRoot, 0);
    copy_eh_kernel<<<2048, 256, 0, s2>>>(
        (const float4*)(eh + CUT), (float4*)(E + CUT),
        (NE * EDIM - CUT) / 4);

    // Main stream: CSR prep
    zero_cnt_kernel<<<(NN + 255) / 256, 256>>>(cnt);
    count_kernel<<<(NE + 255) / 256, 256>>>(dst, cnt);
    scan1_kernel<<<NSCAN, SCAN_BLK>>>(cnt, off, bsum);
    scan2_kernel<<<1, 128>>>(bsum);
    finalize_kernel<<<(NN + 255) / 256, 256>>>(cnt, bsum, off, cur, dis);
    bucket_kernel<<<(NE + 255) / 256, 256>>>(src, dst, cur, esrc);

    // Chunk A aggregate -> MLP(A) forks onto s2, overlapping chunk B aggregate
    aggregate_kernel<<<CHA / 8, 256>>>(nh, esrc, off, cnt, dis, out, 0, CHA);
    cudaEventRecord(evAggA, 0);
    cudaStreamWaitEvent(s2, evAggA, 0);
    mlp_fused_kernel<<<CHA / TILE_M, 128, 0, s2>>>(out, W1, b1, W2, b2, 0);

    aggregate_kernel<<<CHB / 8, 256>>>(nh, esrc, off, cnt, dis, out, CHA, CHB);
    // CSR scratch dead after aggregate B -> copy eh head over it
    copy_eh_kernel<<<1024, 256>>>((const float4*)eh, (float4*)E, CUT / 4);
    mlp_fused_kernel<<<CHB / TILE_M, 128>>>(out, W1, b1, W2, b2, CHA);

    // Join s2 back into the origin stream
    cudaEventRecord(evS2, s2);
    cudaStreamWaitEvent(0, evS2, 0);
}